// round 17
// baseline (speedup 1.0000x reference)
#include <cuda_runtime.h>
#include <cuda_bf16.h>

#define NG 128
#define NT 512
#define SP 28          // padded row stride (floats) = 112B, 16B-aligned
#define NTH 704        // 576 T + 96 H + 32 S

#define BSYNC(id,n)  asm volatile("bar.sync %0, %1;"   :: "n"(id), "r"(n) : "memory")
#define BARRV(id,n)  asm volatile("bar.arrive %0, %1;" :: "n"(id), "r"(n) : "memory")
#define BSYNCR(id,n) asm volatile("bar.sync %0, %1;"   :: "r"(id), "r"(n) : "memory")

typedef unsigned long long u64t;

// packed f32x2 FMA: d = a*b + d (per 32-bit lane)
__device__ __forceinline__ void fma2(u64t& d, u64t a, u64t b) {
    asm("fma.rn.f32x2 %0, %1, %2, %3;" : "=l"(d) : "l"(a), "l"(b), "l"(d));
}
__device__ __forceinline__ u64t add2(u64t a, u64t b) {
    u64t d; asm("add.rn.f32x2 %0, %1, %2;" : "=l"(d) : "l"(a), "l"(b)); return d;
}

// 24-dot: 12 FFMA2 over 4 independent packed chains (depth 3) + packed reduce.
__device__ __forceinline__ float dot24x(const ulonglong2* __restrict__ a,
                                        const ulonglong2* __restrict__ b) {
    u64t a0 = 0ull, a1 = 0ull, a2 = 0ull, a3 = 0ull;
    ulonglong2 x0 = a[0], y0 = b[0], x1 = a[1], y1 = b[1];
    fma2(a0, x0.x, y0.x); fma2(a1, x0.y, y0.y);
    fma2(a2, x1.x, y1.x); fma2(a3, x1.y, y1.y);
    ulonglong2 x2 = a[2], y2 = b[2], x3 = a[3], y3 = b[3];
    fma2(a0, x2.x, y2.x); fma2(a1, x2.y, y2.y);
    fma2(a2, x3.x, y3.x); fma2(a3, x3.y, y3.y);
    ulonglong2 x4 = a[4], y4 = b[4], x5 = a[5], y5 = b[5];
    fma2(a0, x4.x, y4.x); fma2(a1, x4.y, y4.y);
    fma2(a2, x5.x, y5.x); fma2(a3, x5.y, y5.y);
    u64t s = add2(add2(a0, a1), add2(a2, a3));
    float2 f = *reinterpret_cast<float2*>(&s);
    return f.x + f.y;
}
// same with first operand register-cached
__device__ __forceinline__ float dot24rx(const ulonglong2 fr[6],
                                         const ulonglong2* __restrict__ b) {
    u64t a0 = 0ull, a1 = 0ull, a2 = 0ull, a3 = 0ull;
    ulonglong2 y0 = b[0], y1 = b[1];
    fma2(a0, fr[0].x, y0.x); fma2(a1, fr[0].y, y0.y);
    fma2(a2, fr[1].x, y1.x); fma2(a3, fr[1].y, y1.y);
    ulonglong2 y2 = b[2], y3 = b[3];
    fma2(a0, fr[2].x, y2.x); fma2(a1, fr[2].y, y2.y);
    fma2(a2, fr[3].x, y3.x); fma2(a3, fr[3].y, y3.y);
    ulonglong2 y4 = b[4], y5 = b[5];
    fma2(a0, fr[4].x, y4.x); fma2(a1, fr[4].y, y4.y);
    fma2(a2, fr[5].x, y5.x); fma2(a3, fr[5].y, y5.y);
    u64t s = add2(add2(a0, a1), add2(a2, a3));
    float2 f = *reinterpret_cast<float2*>(&s);
    return f.x + f.y;
}

// 4x4 determinant, straight-line, independent chains (no shuffles).
__device__ __forceinline__ float det4(const float* m) {
    float s0 = m[10]*m[15] - m[11]*m[14];
    float s1 = m[9] *m[15] - m[11]*m[13];
    float s2 = m[9] *m[14] - m[10]*m[13];
    float s3 = m[8] *m[15] - m[11]*m[12];
    float s4 = m[8] *m[14] - m[10]*m[12];
    float s5 = m[8] *m[13] - m[9] *m[12];
    float c0 = m[5]*s0 - m[6]*s1 + m[7]*s2;
    float c1 = m[4]*s0 - m[6]*s3 + m[7]*s4;
    float c2 = m[4]*s1 - m[5]*s3 + m[7]*s5;
    float c3 = m[4]*s2 - m[5]*s4 + m[6]*s5;
    return m[0]*c0 - m[1]*c1 + m[2]*c2 - m[3]*c3;
}

__global__ __launch_bounds__(NTH, 1)
void kalman_kernel(const float* __restrict__ y_in,   // (G,T,4)
                   const float* __restrict__ F_in,   // (G,T,24,24)
                   const float* __restrict__ Q_in,   // (G,T,24,24)
                   const float* __restrict__ H_in,   // (G,T,4,24)
                   const float* __restrict__ R_in,   // (G,T,4,4)
                   const float* __restrict__ m0_in,  // (G,24)
                   const float* __restrict__ P0_in,  // (G,24,24)
                   float* __restrict__ out)
{
    __shared__ __align__(16) float P  [24*SP];
    __shared__ __align__(16) float G1 [2][24*SP];  // double-buffered
    __shared__ __align__(16) float Fs [2][24*SP];  // double-buffered
    __shared__ __align__(16) float Hs [2][4*SP];   // double-buffered
    __shared__ __align__(16) float HPs[4*SP];
    __shared__ __align__(16) float Bm [96];        // (F P H^T), row i -> Bm[i*4+q]
    __shared__ __align__(16) float Sinv[16];
    __shared__ __align__(16) float mvec[24];
    __shared__ __align__(16) float Fm [24];
    __shared__ __align__(16) float Sg[16];
    __shared__ float Hm[4];
    __shared__ float ys[2][4];
    __shared__ float v4[4];

    const int tid = threadIdx.x;
    const int g   = blockIdx.x;
    const size_t baseT = (size_t)g * NT;
    float* outMean = out;
    float* outCov  = out + (size_t)NG * NT * 4;

    const int w = tid >> 5, l = tid & 31;

    if (tid < 576) {
        // =================== T role: covariance propagation ===================
        const int ti  = (w % 3) * 8 + (l & 7);
        const int tj  = (w / 3) * 4 + (l >> 3);
        const int blk = w / 3;                     // owns P rows [4blk, 4blk+4)
        const int li  = tid / 24, lj = tid % 24;   // flat coalesced map
        const int bid = 8 + blk;

        P [li*SP+lj]     = P0_in[(size_t)g*576 + tid];
        Fs[0][li*SP+lj]  = F_in[baseT*576 + tid];
        float qCur       = Q_in[baseT*576 + tj*24 + ti];
        if (tid < 24) mvec[tid] = m0_in[g*24 + tid];
        // distance-2 prefetch registers: values for step t+1
        float fA = F_in[(baseT+1)*576 + tid];
        float qA = Q_in[(baseT+1)*576 + tj*24 + ti];
        BSYNC(0, 704);

        const float* pF2 = F_in + (baseT+2)*576 + tid;
        const float* pQ2 = Q_in + (baseT+2)*576 + tj*24 + ti;
        ulonglong2 frow[6];

        for (int t = 0; t < NT-1; ++t) {
            const int cur = t & 1, nxt = cur ^ 1;
            float fB = 0.f, qB = 0.f;
            if (t < NT-2) { fB = *pF2; qB = *pQ2; }
            pF2 += 576; pQ2 += 576;

            // ---- A: G1[ti][tj] = F row ti . P row tj  (P symmetric) ----
            const ulonglong2* fr = (const ulonglong2*)&Fs[cur][ti*SP];
#pragma unroll
            for (int c = 0; c < 6; ++c) frow[c] = fr[c];
            G1[cur][ti*SP+tj] = dot24rx(frow, (const ulonglong2*)&P[tj*SP]);
            BSYNC(1, 576);

            // ---- B: FPF[tj][ti] = G1 row tj . F row ti + Q[tj][ti]; stash F(t+1) ----
            float fpf = qCur + dot24rx(frow, (const ulonglong2*)&G1[cur][tj*SP]);
            Fs[nxt][li*SP+lj] = fA;        // loaded a full iteration ago
            BSYNC(3, 704);                 // wait Bm (H arrive) + Sinv (S sync)

            // ---- D: P[tj][ti] = fpf - b_i Sinv b_j^T ----
            float4 si0 = *(const float4*)&Sinv[0];
            float4 si1 = *(const float4*)&Sinv[4];
            float4 si2 = *(const float4*)&Sinv[8];
            float4 si3 = *(const float4*)&Sinv[12];
            float4 bi  = *(const float4*)&Bm[ti*4];
            float u0 = bi.x*si0.x + bi.y*si1.x + bi.z*si2.x + bi.w*si3.x;
            float u1 = bi.x*si0.y + bi.y*si1.y + bi.z*si2.y + bi.w*si3.y;
            float u2 = bi.x*si0.z + bi.y*si1.z + bi.z*si2.z + bi.w*si3.z;
            float u3 = bi.x*si0.w + bi.y*si1.w + bi.z*si2.w + bi.w*si3.w;
            float4 bj = *(const float4*)&Bm[tj*4];
            float corr = u0*bj.x + u1*bj.y + u2*bj.z + u3*bj.w;
            P[tj*SP+ti] = fpf - corr;

            // rotate prefetch registers
            qCur = qA; qA = qB; fA = fB;

            BARRV(7, 672);                 // let H see completed P
            BSYNCR(bid, 96);               // only our tj-block must converge
        }
        // T not needed for the final step's outputs.
    } else if (tid < 672) {
        // =================== H role: HP = H P,  Bm = F (HP)^T ===================
        const int u = tid - 576, uq = u / 24, us = u % 24;

        Hs[0][uq*SP + us] = H_in[baseT*96 + u];
        float hA = H_in[(baseT+1)*96 + u];     // value for step t+1
        BSYNC(0, 704);

        const float* pH2 = H_in + (baseT+2)*96 + u;

        for (int t = 0; t < NT-1; ++t) {
            const int cur = t & 1, nxt = cur ^ 1;
            float hB = 0.f;
            if (t < NT-2) hB = *pH2;
            pH2 += 96;

            HPs[uq*SP+us] = dot24x((const ulonglong2*)&Hs[cur][uq*SP],
                                   (const ulonglong2*)&P[us*SP]);
            BSYNC(2, 128);

            Bm[us*4 + uq] = dot24x((const ulonglong2*)&Fs[cur][us*SP],
                                   (const ulonglong2*)&HPs[uq*SP]);
            Hs[nxt][uq*SP + us] = hA;      // loaded a full iteration ago
            hA = hB;
            BARRV(4, 128);                 // S may read Bm
            BARRV(3, 704);                 // T may read Bm
            BSYNC(7, 672);                 // wait for new P before next HP
        }
        // epilogue t = NT-1: HP for the final Sigma
        {
            const int cur = (NT-1) & 1;
            HPs[uq*SP+us] = dot24x((const ulonglong2*)&Hs[cur][uq*SP],
                                   (const ulonglong2*)&P[us*SP]);
            BSYNC(2, 128);
        }
    } else {
        // =================== S role: measurement, inverse, mean ===================
        const int sl = tid - 672;

        int ca=0, cb=0, r0=0, r1=0, r2=0, c0=0, c1=0, c2=0; float csign = 1.f;
        if (sl < 16) {
            ca = sl >> 2; cb = sl & 3;
            r0 = (ca==0)?1:0; r1 = (ca<=1)?2:1; r2 = (ca<=2)?3:2;
            c0 = (cb==0)?1:0; c1 = (cb<=1)?2:1; c2 = (cb<=2)?3:2;
            csign = ((ca+cb)&1) ? -1.f : 1.f;
        }

        float rCur = 0.f, rA = 0.f, yA = 0.f;
        if (sl < 16) {
            rCur = R_in[baseT*16 + sl];
            rA   = R_in[(baseT+1)*16 + sl];
        } else if (sl < 20) {
            ys[0][sl-16] = y_in[baseT*4 + (sl-16)];
            yA           = y_in[(baseT+1)*4 + (sl-16)];
        }
        BSYNC(0, 704);

        const float* pR2 = R_in + (baseT+2)*16 + sl;
        const float* pY2 = y_in + (baseT+2)*4  + (sl - 16);

        for (int t = 0; t < NT-1; ++t) {
            const int cur = t & 1, nxt = cur ^ 1;
            float rB = 0.f, yB = 0.f;
            if (t < NT-2) {
                if (sl < 16)      rB = *pR2;
                else if (sl < 20) yB = *pY2;
            }
            pR2 += 16; pY2 += 4;

            // ---- A: Hm (-> mean out), Fm ----
            if (sl < 4) {
                float hm = dot24x((const ulonglong2*)&Hs[cur][sl*SP], (const ulonglong2*)mvec);
                Hm[sl] = hm;
                outMean[(baseT+t)*4 + sl] = hm;
            } else if (sl < 28) {
                int i = sl - 4;
                Fm[i] = dot24x((const ulonglong2*)&Fs[cur][i*SP], (const ulonglong2*)mvec);
            }
            BSYNC(2, 128);

            // ---- B: Sm -> Sig out; Sinv (redundant det, no shuffles) ----
            if (sl < 16) {
                int q = sl >> 2, r = sl & 3;
                float sm = rCur + dot24x((const ulonglong2*)&HPs[q*SP],
                                         (const ulonglong2*)&Hs[cur][r*SP]);
                Sg[sl] = sm;
                outCov[(baseT+t)*16 + sl] = sm;
            }
            __syncwarp();
            if (sl < 16) {
                const float* m = Sg;
                float m00=m[r0*4+c0], m01=m[r0*4+c1], m02=m[r0*4+c2];
                float m10=m[r1*4+c0], m11=m[r1*4+c1], m12=m[r1*4+c2];
                float m20=m[r2*4+c0], m21=m[r2*4+c1], m22=m[r2*4+c2];
                float d3 = m00*(m11*m22 - m12*m21)
                         - m01*(m10*m22 - m12*m20)
                         + m02*(m10*m21 - m11*m20);
                float det = det4(m);
                Sinv[cb*4+ca] = csign * d3 * (1.0f / det);
            }
            BSYNC(3, 704);                 // publish Sinv; also orders T's Fs stash
            BSYNC(4, 128);                 // wait Bm from H

            // ---- D (off critical path): v4, m' ----
            if (sl < 4) {
                const float* si = &Sinv[sl*4];
                const float* yb = ys[cur];
                v4[sl] = si[0]*(yb[0]-Hm[0]) + si[1]*(yb[1]-Hm[1])
                       + si[2]*(yb[2]-Hm[2]) + si[3]*(yb[3]-Hm[3]);
            }
            __syncwarp();
            if (sl < 24) {
                mvec[sl] = Fm[sl] + Bm[sl*4+0]*v4[0] + Bm[sl*4+1]*v4[1]
                         + Bm[sl*4+2]*v4[2] + Bm[sl*4+3]*v4[3];
            }
            rCur = rA; rA = rB;
            if (sl >= 16 && sl < 20) ys[nxt][sl-16] = yA;
            yA = yB;
            __syncwarp();                  // mvec visible to next A
        }
        // epilogue t = NT-1: final mean + Sigma
        {
            const int cur = (NT-1) & 1;
            if (sl < 4) {
                float hm = dot24x((const ulonglong2*)&Hs[cur][sl*SP], (const ulonglong2*)mvec);
                outMean[(baseT+NT-1)*4 + sl] = hm;
            }
            BSYNC(2, 128);
            if (sl < 16) {
                int q = sl >> 2, r = sl & 3;
                float sm = rCur + dot24x((const ulonglong2*)&HPs[q*SP],
                                         (const ulonglong2*)&Hs[cur][r*SP]);
                outCov[(baseT+NT-1)*16 + sl] = sm;
            }
        }
    }
}

extern "C" void kernel_launch(void* const* d_in, const int* in_sizes, int n_in,
                              void* d_out, int out_size) {
    const float* y  = (const float*)d_in[0];
    const float* F  = (const float*)d_in[1];
    const float* Q  = (const float*)d_in[2];
    const float* H  = (const float*)d_in[3];
    const float* R  = (const float*)d_in[4];
    const float* m0 = (const float*)d_in[5];
    const float* P0 = (const float*)d_in[6];
    kalman_kernel<<<NG, NTH>>>(y, F, Q, H, R, m0, P0, (float*)d_out);
}